// round 11
// baseline (speedup 1.0000x reference)
#include <cuda_runtime.h>
#include <cuda_bf16.h>
#include <stdint.h>
#include <math.h>

// Problem constants
#define BATCH 8
#define SEQ   128
#define NTOK  (BATCH * SEQ)      // 1024
#define DIM   512
#define NHEAD 8
#define HD    64
#define FF    1024
#define OUTD  1000
#define NLAYER 2
#define NSTEPS 20
#define ALPHA_ 0.5f
#define QKVN  (3 * DIM)          // 1536

// ---------------- scratch (device globals; no allocation) ----------------
__device__ float g_xemb[NTOK * DIM];
__device__ float g_h[NTOK * DIM];

__device__ __nv_bfloat16 g_qkv_hi[NTOK * QKVN];
__device__ __nv_bfloat16 g_qkv_lo[NTOK * QKVN];
__device__ __nv_bfloat16 g_o_hi[NTOK * DIM];
__device__ __nv_bfloat16 g_o_lo[NTOK * DIM];
__device__ __nv_bfloat16 g_f1_hi[NTOK * FF];
__device__ __nv_bfloat16 g_f1_lo[NTOK * FF];

// split weights (converted once per launch call)
__device__ __nv_bfloat16 g_Wqkv_hi[NLAYER * DIM * QKVN];
__device__ __nv_bfloat16 g_Wqkv_lo[NLAYER * DIM * QKVN];
__device__ float         g_bqkv  [NLAYER * QKVN];
__device__ __nv_bfloat16 g_Wo_hi[NLAYER * DIM * DIM];
__device__ __nv_bfloat16 g_Wo_lo[NLAYER * DIM * DIM];
__device__ __nv_bfloat16 g_W1_hi[NLAYER * DIM * FF];
__device__ __nv_bfloat16 g_W1_lo[NLAYER * DIM * FF];
__device__ __nv_bfloat16 g_W2_hi[NLAYER * FF * DIM];
__device__ __nv_bfloat16 g_W2_lo[NLAYER * FF * DIM];

__device__ __forceinline__ void split2(float x, __nv_bfloat16& hi, __nv_bfloat16& lo) {
    hi = __float2bfloat16(x);
    lo = __float2bfloat16(x - __bfloat162float(hi));
}
__device__ __forceinline__ unsigned pack_bf2(__nv_bfloat16 a, __nv_bfloat16 b) {
    __nv_bfloat162 t; t.x = a; t.y = b;
    return *(unsigned*)&t;
}

// ---------------- weight conversion ----------------
__global__ void pack_qkv_kernel(const float* __restrict__ Wq, const float* __restrict__ Wk,
                                const float* __restrict__ Wv, const float* __restrict__ bq,
                                const float* __restrict__ bk, const float* __restrict__ bv,
                                __nv_bfloat16* __restrict__ Wh, __nv_bfloat16* __restrict__ Wl,
                                float* __restrict__ bias) {
    int i = blockIdx.x * 256 + threadIdx.x;
    int layer = i / (DIM * QKVN);
    int rem = i % (DIM * QKVN);
    int r = rem / QKVN, c = rem % QKVN;
    const float* src = (c < DIM) ? Wq : (c < 2 * DIM) ? Wk : Wv;
    float v = src[layer * DIM * DIM + r * DIM + (c & (DIM - 1))];
    split2(v, Wh[i], Wl[i]);
    if (i < NLAYER * QKVN) {
        int l2 = i / QKVN, c2 = i % QKVN;
        const float* bsrc = (c2 < DIM) ? bq : (c2 < 2 * DIM) ? bk : bv;
        bias[i] = bsrc[l2 * DIM + (c2 & (DIM - 1))];
    }
}

__global__ void conv_split_kernel(const float* __restrict__ src,
                                  __nv_bfloat16* __restrict__ hi,
                                  __nv_bfloat16* __restrict__ lo, int n) {
    int i = blockIdx.x * 256 + threadIdx.x;
    if (i < n) split2(src[i], hi[i], lo[i]);
}

// ---------------- embed + zero h ----------------
__global__ void embed_kernel(const int* __restrict__ x, const float* __restrict__ tok,
                             const float* __restrict__ pos, float* __restrict__ xemb,
                             float* __restrict__ h) {
    int i = blockIdx.x * blockDim.x + threadIdx.x;
    int token = i >> 9;
    int d = i & 511;
    int s = token & (SEQ - 1);
    xemb[i] = tok[(long)x[token] * DIM + d] + pos[s * DIM + d];
    h[i] = 0.0f;
}

// ---------------- MMA primitives (validated R3/R4/R9) ----------------
#define LDSM4(R0,R1,R2,R3,ADDR) \
    asm volatile("ldmatrix.sync.aligned.m8n8.x4.shared.b16 {%0,%1,%2,%3},[%4];" \
                 : "=r"(R0),"=r"(R1),"=r"(R2),"=r"(R3) : "r"(ADDR))
#define LDSM4T(R0,R1,R2,R3,ADDR) \
    asm volatile("ldmatrix.sync.aligned.m8n8.x4.trans.shared.b16 {%0,%1,%2,%3},[%4];" \
                 : "=r"(R0),"=r"(R1),"=r"(R2),"=r"(R3) : "r"(ADDR))
#define MMA16816(D,A,B0,B1) \
    asm volatile("mma.sync.aligned.m16n8k16.row.col.f32.bf16.bf16.f32 " \
                 "{%0,%1,%2,%3},{%4,%5,%6,%7},{%8,%9},{%0,%1,%2,%3};" \
                 : "+f"((D)[0]),"+f"((D)[1]),"+f"((D)[2]),"+f"((D)[3]) \
                 : "r"((A)[0]),"r"((A)[1]),"r"((A)[2]),"r"((A)[3]),"r"(B0),"r"(B1))

// ---------------- tensor-core GEMM (bf16 2-term split, fp32 accum) ----------------
// R9-proven structure. LN=true: A from fp32 hsrc with fused layernorm (K must be DIM);
// A-path uses ONLY scalar float loads and 4-byte smem stores (hazard-minimized).
// modes: 1: relu+split  2: Cf=v+res  3: eqprop update  4: split (no relu)
template<int TM, bool LN>
__global__ __launch_bounds__(256)
void gemm_tc(const __nv_bfloat16* __restrict__ Ah, const __nv_bfloat16* __restrict__ Al,
             const float* __restrict__ hsrc, const float* __restrict__ lng,
             const float* __restrict__ lnb,
             const __nv_bfloat16* __restrict__ Bh, const __nv_bfloat16* __restrict__ Bl,
             const float* __restrict__ bias, const float* __restrict__ res,
             float* __restrict__ Cf, __nv_bfloat16* __restrict__ Ch,
             __nv_bfloat16* __restrict__ Cl, const float* __restrict__ xemb,
             int K, int N, int mode) {
    constexpr int NW  = (TM == 128) ? 4 : 2;   // n8 tiles per warp
    constexpr int WMW = TM / 32;               // warps along M
    __shared__ __align__(16) __nv_bfloat16 sAh[TM][40], sAl[TM][40];
    __shared__ __align__(16) __nv_bfloat16 sBh[32][72],  sBl[32][72];
    __shared__ float sMu[TM], sRs[TM];

    int tid = threadIdx.x;
    int m0 = blockIdx.y * TM, n0 = blockIdx.x * 64;
    int warp = tid >> 5, lane = tid & 31;
    int wm = (warp % WMW) * 32;
    int wn = (warp / WMW) * (NW * 8);

    // ---- LN prologue: per-row mu, rsig (scalar loads + shfl only) ----
    if (LN) {
        constexpr int RPW = TM / 8;            // rows per warp
        #pragma unroll
        for (int i = 0; i < RPW; i++) {
            int r = warp * RPW + i;
            const float* hr = hsrc + (size_t)(m0 + r) * DIM;
            float s = 0.0f;
            #pragma unroll
            for (int j = 0; j < 16; j++) s += hr[lane + 32 * j];
            #pragma unroll
            for (int o = 16; o; o >>= 1) s += __shfl_xor_sync(0xffffffffu, s, o);
            float mu = s * (1.0f / DIM);
            float vs = 0.0f;
            #pragma unroll
            for (int j = 0; j < 16; j++) {
                float dv = hr[lane + 32 * j] - mu;
                vs += dv * dv;
            }
            #pragma unroll
            for (int o = 16; o; o >>= 1) vs += __shfl_xor_sync(0xffffffffu, vs, o);
            if (lane == 0) {
                sMu[r] = mu;
                sRs[r] = rsqrtf(vs * (1.0f / DIM) + 1e-5f);
            }
        }
        __syncthreads();
    }

    float d[2][NW][4];
    #pragma unroll
    for (int a = 0; a < 2; a++)
        #pragma unroll
        for (int bb = 0; bb < NW; bb++)
            #pragma unroll
            for (int c = 0; c < 4; c++) d[a][bb][c] = 0.0f;

    for (int k0 = 0; k0 < K; k0 += 32) {
        if (LN) {
            // 4 threads per row, 8 cols each: r = idx>>2, kc = (idx&3)*8
            #pragma unroll
            for (int i = 0; i < TM / 64; i++) {
                int idx = tid + i * 256;
                int r = idx >> 2, kc = (idx & 3) * 8;
                float mu = sMu[r], rs = sRs[r];
                const float* hr = hsrc + (size_t)(m0 + r) * DIM + k0 + kc;
                unsigned* dsth = (unsigned*)&sAh[r][kc];
                unsigned* dstl = (unsigned*)&sAl[r][kc];
                #pragma unroll
                for (int p = 0; p < 4; p++) {
                    float f0 = hr[2 * p];
                    float f1 = hr[2 * p + 1];
                    float n0 = (f0 - mu) * rs * lng[k0 + kc + 2 * p]     + lnb[k0 + kc + 2 * p];
                    float n1 = (f1 - mu) * rs * lng[k0 + kc + 2 * p + 1] + lnb[k0 + kc + 2 * p + 1];
                    __nv_bfloat16 h0, l0, h1, l1;
                    split2(n0, h0, l0);
                    split2(n1, h1, l1);
                    dsth[p] = pack_bf2(h0, h1);   // 4-byte smem store
                    dstl[p] = pack_bf2(l0, l1);
                }
            }
        } else {
            #pragma unroll
            for (int i = 0; i < TM / 64; i++) {
                int idx = tid + i * 256;
                int r = idx >> 2, kc = (idx & 3) * 8;
                size_t go = (size_t)(m0 + r) * K + k0 + kc;
                *(uint4*)&sAh[r][kc] = *(const uint4*)(Ah + go);
                *(uint4*)&sAl[r][kc] = *(const uint4*)(Al + go);
            }
        }
        {
            int r = tid >> 3, nc = (tid & 7) * 8;
            size_t go = (size_t)(k0 + r) * N + n0 + nc;
            *(uint4*)&sBh[r][nc] = *(const uint4*)(Bh + go);
            *(uint4*)&sBl[r][nc] = *(const uint4*)(Bl + go);
        }
        __syncthreads();

        #pragma unroll
        for (int kk = 0; kk < 32; kk += 16) {
            unsigned ah[2][4], al[2][4], bh[2][4], bl[2][4];
            #pragma unroll
            for (int mi = 0; mi < 2; mi++) {
                unsigned adh = (unsigned)__cvta_generic_to_shared(
                    &sAh[wm + mi * 16 + (lane & 15)][kk + (lane >> 4) * 8]);
                LDSM4(ah[mi][0], ah[mi][1], ah[mi][2], ah[mi][3], adh);
                unsigned adl = (unsigned)__cvta_generic_to_shared(
                    &sAl[wm + mi * 16 + (lane & 15)][kk + (lane >> 4) * 8]);
                LDSM4(al[mi][0], al[mi][1], al[mi][2], al[mi][3], adl);
            }
            #pragma unroll
            for (int nj = 0; nj < NW / 2; nj++) {
                unsigned bdh = (unsigned)__cvta_generic_to_shared(
                    &sBh[kk + (lane & 15)][wn + nj * 16 + (lane >> 4) * 8]);
                LDSM4T(bh[nj][0], bh[nj][1], bh[nj][2], bh[nj][3], bdh);
                unsigned bdl = (unsigned)__cvta_generic_to_shared(
                    &sBl[kk + (lane & 15)][wn + nj * 16 + (lane >> 4) * 8]);
                LDSM4T(bl[nj][0], bl[nj][1], bl[nj][2], bl[nj][3], bdl);
            }
            #pragma unroll
            for (int mi = 0; mi < 2; mi++)
                #pragma unroll
                for (int n8 = 0; n8 < NW; n8++) {
                    unsigned b0h = bh[n8 >> 1][(n8 & 1) * 2 + 0];
                    unsigned b1h = bh[n8 >> 1][(n8 & 1) * 2 + 1];
                    unsigned b0l = bl[n8 >> 1][(n8 & 1) * 2 + 0];
                    unsigned b1l = bl[n8 >> 1][(n8 & 1) * 2 + 1];
                    MMA16816(d[mi][n8], ah[mi], b0h, b1h);
                    MMA16816(d[mi][n8], ah[mi], b0l, b1l);
                    MMA16816(d[mi][n8], al[mi], b0h, b1h);
                }
        }
        __syncthreads();
    }

    // epilogue (R9 verbatim)
    #pragma unroll
    for (int mi = 0; mi < 2; mi++)
        #pragma unroll
        for (int n8 = 0; n8 < NW; n8++) {
            int r0 = m0 + wm + mi * 16 + (lane >> 2);
            int c0 = n0 + wn + n8 * 8 + (lane & 3) * 2;
            float b0v = bias[c0], b1v = bias[c0 + 1];
            #pragma unroll
            for (int half = 0; half < 2; half++) {
                int rr = r0 + half * 8;
                float v0 = d[mi][n8][half * 2 + 0] + b0v;
                float v1 = d[mi][n8][half * 2 + 1] + b1v;
                size_t idx = (size_t)rr * N + c0;
                if (mode == 1) {
                    v0 = fmaxf(v0, 0.0f); v1 = fmaxf(v1, 0.0f);
                    split2(v0, Ch[idx], Cl[idx]);
                    split2(v1, Ch[idx + 1], Cl[idx + 1]);
                } else if (mode == 2) {
                    Cf[idx] = v0 + res[idx]; Cf[idx + 1] = v1 + res[idx + 1];
                } else if (mode == 3) {
                    float h0 = res[idx], h1 = res[idx + 1];
                    float t0 = h0 + v0 + xemb[idx];
                    float t1 = h1 + v1 + xemb[idx + 1];
                    Cf[idx]     = h0 + ALPHA_ * (tanhf(t0) - h0);
                    Cf[idx + 1] = h1 + ALPHA_ * (tanhf(t1) - h1);
                } else { // 4: split, no relu
                    split2(v0, Ch[idx], Cl[idx]);
                    split2(v1, Ch[idx + 1], Cl[idx + 1]);
                }
            }
        }
}

// ---------------- fused tensor-core attention (R4/R9 verbatim) ----------------
__global__ __launch_bounds__(256)
void attn_kernel(const __nv_bfloat16* __restrict__ qkv_hi,
                 const __nv_bfloat16* __restrict__ qkv_lo,
                 __nv_bfloat16* __restrict__ o_hi, __nv_bfloat16* __restrict__ o_lo) {
    extern __shared__ char sm_raw[];
    __nv_bfloat16* sQh = (__nv_bfloat16*)sm_raw;            // [64][72]
    __nv_bfloat16* sQl = sQh + 64 * 72;
    __nv_bfloat16* sKh = sQl + 64 * 72;                     // K^T [64 d][136 s]
    __nv_bfloat16* sKl = sKh + 64 * 136;
    __nv_bfloat16* sVh = sKl + 64 * 136;                    // [128 s][72 d]
    __nv_bfloat16* sVl = sVh + 128 * 72;
    float* sO   = (float*)(sVl + 128 * 72);                 // [4 mt][16][64]
    float* sMax = sO + 4 * 16 * 64;
    float* sSum = sMax + 128;

    int blk = blockIdx.x;
    int bh = blk >> 1, qhalf = blk & 1;
    int b = bh >> 3, hh = bh & 7;
    int tid = threadIdx.x, warp = tid >> 5, lane = tid & 31;
    int q0 = qhalf * 64;

    for (int i = tid; i < 64 * 64; i += 256) {
        int r = i >> 6, dd = i & 63;
        size_t g = (size_t)(b * SEQ + q0 + r) * QKVN + hh * HD + dd;
        sQh[r * 72 + dd] = qkv_hi[g];
        sQl[r * 72 + dd] = qkv_lo[g];
    }
    for (int i = tid; i < 128 * 64; i += 256) {
        int s = i >> 6, dd = i & 63;
        size_t g = (size_t)(b * SEQ + s) * QKVN + DIM + hh * HD + dd;
        sKh[dd * 136 + s] = qkv_hi[g];
        sKl[dd * 136 + s] = qkv_lo[g];
    }
    for (int i = tid; i < 128 * 64; i += 256) {
        int s = i >> 6, dd = i & 63;
        size_t g = (size_t)(b * SEQ + s) * QKVN + 2 * DIM + hh * HD + dd;
        sVh[s * 72 + dd] = qkv_hi[g];
        sVl[s * 72 + dd] = qkv_lo[g];
    }
    __syncthreads();

    int mt = warp >> 1;
    int kh = warp & 1;

    float s[8][4];
    #pragma unroll
    for (int a = 0; a < 8; a++)
        #pragma unroll
        for (int c = 0; c < 4; c++) s[a][c] = 0.0f;

    #pragma unroll
    for (int d0 = 0; d0 < 64; d0 += 16) {
        unsigned qh4[4], ql4[4];
        unsigned aaddr = (unsigned)__cvta_generic_to_shared(
            &sQh[(mt * 16 + (lane & 15)) * 72 + d0 + (lane >> 4) * 8]);
        LDSM4(qh4[0], qh4[1], qh4[2], qh4[3], aaddr);
        unsigned aaddr2 = (unsigned)__cvta_generic_to_shared(
            &sQl[(mt * 16 + (lane & 15)) * 72 + d0 + (lane >> 4) * 8]);
        LDSM4(ql4[0], ql4[1], ql4[2], ql4[3], aaddr2);
        #pragma unroll
        for (int nj = 0; nj < 4; nj++) {
            unsigned kbh[4], kbl[4];
            unsigned baddr = (unsigned)__cvta_generic_to_shared(
                &sKh[(d0 + (lane & 15)) * 136 + kh * 64 + nj * 16 + (lane >> 4) * 8]);
            LDSM4T(kbh[0], kbh[1], kbh[2], kbh[3], baddr);
            unsigned baddr2 = (unsigned)__cvta_generic_to_shared(
                &sKl[(d0 + (lane & 15)) * 136 + kh * 64 + nj * 16 + (lane >> 4) * 8]);
            LDSM4T(kbl[0], kbl[1], kbl[2], kbl[3], baddr2);
            MMA16816(s[2 * nj],     qh4, kbh[0], kbh[1]);
            MMA16816(s[2 * nj],     qh4, kbl[0], kbl[1]);
            MMA16816(s[2 * nj],     ql4, kbh[0], kbh[1]);
            MMA16816(s[2 * nj + 1], qh4, kbh[2], kbh[3]);
            MMA16816(s[2 * nj + 1], qh4, kbl[2], kbl[3]);
            MMA16816(s[2 * nj + 1], ql4, kbh[2], kbh[3]);
        }
    }

    const float scale = 0.125f;
    float mlo = -1e30f, mhi = -1e30f;
    #pragma unroll
    for (int n8 = 0; n8 < 8; n8++) {
        #pragma unroll
        for (int c = 0; c < 4; c++) s[n8][c] *= scale;
        mlo = fmaxf(mlo, fmaxf(s[n8][0], s[n8][1]));
        mhi = fmaxf(mhi, fmaxf(s[n8][2], s[n8][3]));
    }
    #pragma unroll
    for (int o = 1; o <= 2; o <<= 1) {
        mlo = fmaxf(mlo, __shfl_xor_sync(0xffffffffu, mlo, o));
        mhi = fmaxf(mhi, __shfl_xor_sync(0xffffffffu, mhi, o));
    }
    int rl = lane >> 2;
    if ((lane & 3) == 0) {
        sMax[(mt * 2 + kh) * 16 + rl]     = mlo;
        sMax[(mt * 2 + kh) * 16 + rl + 8] = mhi;
    }
    __syncthreads();
    float Ml = fmaxf(sMax[mt * 32 + rl],     sMax[mt * 32 + 16 + rl]);
    float Mh = fmaxf(sMax[mt * 32 + 8 + rl], sMax[mt * 32 + 24 + rl]);

    float slo = 0.0f, shi = 0.0f;
    #pragma unroll
    for (int n8 = 0; n8 < 8; n8++) {
        s[n8][0] = __expf(s[n8][0] - Ml); slo += s[n8][0];
        s[n8][1] = __expf(s[n8][1] - Ml); slo += s[n8][1];
        s[n8][2] = __expf(s[n8][2] - Mh); shi += s[n8][2];
        s[n8][3] = __expf(s[n8][3] - Mh); shi += s[n8][3];
    }
    #pragma unroll
    for (int o = 1; o <= 2; o <<= 1) {
        slo += __shfl_xor_sync(0xffffffffu, slo, o);
        shi += __shfl_xor_sync(0xffffffffu, shi, o);
    }
    if ((lane & 3) == 0) {
        sSum[(mt * 2 + kh) * 16 + rl]     = slo;
        sSum[(mt * 2 + kh) * 16 + rl + 8] = shi;
    }
    __syncthreads();
    float invl = 1.0f / (sSum[mt * 32 + rl]     + sSum[mt * 32 + 16 + rl]);
    float invh = 1.0f / (sSum[mt * 32 + 8 + rl] + sSum[mt * 32 + 24 + rl]);

    float o_acc[8][4];
    #pragma unroll
    for (int a = 0; a < 8; a++)
        #pragma unroll
        for (int c = 0; c < 4; c++) o_acc[a][c] = 0.0f;

    #pragma unroll
    for (int kk = 0; kk < 4; kk++) {
        float p[8];
        p[0] = s[2 * kk][0] * invl;     p[1] = s[2 * kk][1] * invl;
        p[2] = s[2 * kk][2] * invh;     p[3] = s[2 * kk][3] * invh;
        p[4] = s[2 * kk + 1][0] * invl; p[5] = s[2 * kk + 1][1] * invl;
        p[6] = s[2 * kk + 1][2] * invh; p[7] = s[2 * kk + 1][3] * invh;
        __nv_bfloat16 phh[8], pll[8];
        #pragma unroll
        for (int j = 0; j < 8; j++) split2(p[j], phh[j], pll[j]);
        unsigned pah[4], pal[4];
        #pragma unroll
        for (int j = 0; j < 4; j++) {
            pah[j] = pack_bf2(phh[2 * j], phh[2 * j + 1]);
            pal[j] = pack_bf2(pll[2 * j], pll[2 * j + 1]);
        }
        #pragma unroll
        for (int nj = 0; nj < 4; nj++) {
            unsigned vbh[4], vbl[4];
            unsigned baddr = (unsigned)__cvta_generic_to_shared(
                &sVh[(kh * 64 + kk * 16 + (lane & 15)) * 72 + nj * 16 + (lane >> 4) * 8]);
            LDSM4T(vbh[0], vbh[1], vbh[2], vbh[3], baddr);
            unsigned baddr2 = (unsigned)__cvta_generic_to_shared(
                &sVl[(kh * 64 + kk * 16 + (lane & 15)) * 72 + nj * 16 + (lane >> 4) * 8]);
            LDSM4T(vbl[0], vbl[1], vbl[2], vbl[3], baddr2);
            MMA16816(o_acc[2 * nj],     pah, vbh[0], vbh[1]);
            MMA16816(o_acc[2 * nj],     pah, vbl[0], vbl[1]);
            MMA16816(o_acc[2 * nj],     pal, vbh[0], vbh[1]);
            MMA16816(o_acc[2 * nj + 1], pah, vbh[2], vbh[3]);
            MMA16816(o_acc[2 * nj + 1], pah, vbl[2], vbl[3]);
            MMA16816(o_acc[2 * nj + 1], pal, vbh[2], vbh[3]);
        }
    }

    if (kh == 1) {
        #pragma unroll
        for (int n8 = 0; n8 < 8; n8++) {
            int c = n8 * 8 + (lane & 3) * 2;
            sO[mt * 1024 + rl * 64 + c]           = o_acc[n8][0];
            sO[mt * 1024 + rl * 64 + c + 1]       = o_acc[n8][1];
            sO[mt * 1024 + (rl + 8) * 64 + c]     = o_acc[n8][2];
            sO[mt * 1024 + (rl + 8) * 64 + c + 1] = o_acc[n8][3];
        }
    }
    __syncthreads();
    if (kh == 0) {
        #pragma unroll
        for (int n8 = 0; n8 < 8; n8++) {
            int c = n8 * 8 + (lane & 3) * 2;
            float v0 = o_acc[n8][0] + sO[mt * 1024 + rl * 64 + c];
            float v1 = o_acc[n8][1] + sO[mt * 1024 + rl * 64 + c + 1];
            float v2 = o_acc[n8][2] + sO[mt * 1024 + (rl + 8) * 64 + c];
            float v3 = o_acc[n8][3] + sO[mt * 1024 + (rl + 8) * 64 + c + 1];
            size_t g0 = (size_t)(b * SEQ + q0 + mt * 16 + rl) * DIM + hh * HD + c;
            size_t g1 = (size_t)(b * SEQ + q0 + mt * 16 + rl + 8) * DIM + hh * HD + c;
            split2(v0, o_hi[g0], o_lo[g0]);
            split2(v1, o_hi[g0 + 1], o_lo[g0 + 1]);
            split2(v2, o_hi[g1], o_lo[g1]);
            split2(v3, o_hi[g1 + 1], o_lo[g1 + 1]);
        }
    }
}

// ---------------- fused mean-pool + head (R9, passing) ----------------
__global__ void pool_head_kernel(const float* __restrict__ h, const float* __restrict__ W,
                                 const float* __restrict__ bias, float* __restrict__ out) {
    __shared__ float sp[DIM];
    int b = blockIdx.x;                  // 8 blocks
    int tid = threadIdx.x;               // 512
    float s = 0.0f;
    for (int si = 0; si < SEQ; si++) s += h[(b * SEQ + si) * DIM + tid];
    sp[tid] = s * (1.0f / SEQ);
    __syncthreads();
    for (int o = tid; o < OUTD; o += 512) {
        float acc = bias[o];
        #pragma unroll 4
        for (int d = 0; d < DIM; d++) acc += sp[d] * W[d * OUTD + o];
        out[b * OUTD + o] = acc;
    }
}

// ---------------- launch ----------------
extern "C" void kernel_launch(void* const* d_in, const int* in_sizes, int n_in,
                              void* d_out, int out_size) {
    const int*   x       = (const int*)  d_in[0];
    // d_in[1] = steps (fixed 20; unrolled on host)
    const float* tok_emb = (const float*)d_in[2];
    const float* pos_emb = (const float*)d_in[3];
    const float* Wq = (const float*)d_in[4];
    const float* bq = (const float*)d_in[5];
    const float* Wk = (const float*)d_in[6];
    const float* bk = (const float*)d_in[7];
    const float* Wv = (const float*)d_in[8];
    const float* bv = (const float*)d_in[9];
    const float* Wo = (const float*)d_in[10];
    const float* bo = (const float*)d_in[11];
    const float* W1 = (const float*)d_in[12];
    const float* b1 = (const float*)d_in[13];
    const float* W2 = (const float*)d_in[14];
    const float* b2 = (const float*)d_in[15];
    const float* ln1_g = (const float*)d_in[16];
    const float* ln1_b = (const float*)d_in[17];
    const float* ln2_g = (const float*)d_in[18];
    const float* ln2_b = (const float*)d_in[19];
    const float* head_w = (const float*)d_in[20];
    const float* head_b = (const float*)d_in[21];
    float* out = (float*)d_out;

    float *xemb, *h, *bqkv;
    __nv_bfloat16 *qkv_hi, *qkv_lo, *o_hi, *o_lo, *f1_hi, *f1_lo;
    __nv_bfloat16 *Wqkv_hi, *Wqkv_lo, *Wo_hi, *Wo_lo, *W1_hi, *W1_lo, *W2_hi, *W2_lo;
    cudaGetSymbolAddress((void**)&xemb,   g_xemb);
    cudaGetSymbolAddress((void**)&h,      g_h);
    cudaGetSymbolAddress((void**)&bqkv,   g_bqkv);
    cudaGetSymbolAddress((void**)&qkv_hi, g_qkv_hi);
    cudaGetSymbolAddress((void**)&qkv_lo, g_qkv_lo);
    cudaGetSymbolAddress((void**)&o_hi,   g_o_hi);
    cudaGetSymbolAddress((void**)&o_lo,   g_o_lo);
    cudaGetSymbolAddress((void**)&f1_hi,  g_f1_hi);
    cudaGetSymbolAddress((void**)&f1_lo,  g_f1_lo);
    cudaGetSymbolAddress((void**)&Wqkv_hi, g_Wqkv_hi);
    cudaGetSymbolAddress((void**)&Wqkv_lo, g_Wqkv_lo);
    cudaGetSymbolAddress((void**)&Wo_hi,  g_Wo_hi);
    cudaGetSymbolAddress((void**)&Wo_lo,  g_Wo_lo);
    cudaGetSymbolAddress((void**)&W1_hi,  g_W1_hi);
    cudaGetSymbolAddress((void**)&W1_lo,  g_W1_lo);
    cudaGetSymbolAddress((void**)&W2_hi,  g_W2_hi);
    cudaGetSymbolAddress((void**)&W2_lo,  g_W2_lo);

    const int ATTN_SMEM = (2 * (64 * 72) + 2 * (64 * 136) + 2 * (128 * 72)) * 2
                        + (4 * 16 * 64 + 256) * 4;   // 107,520 B
    cudaFuncSetAttribute(attn_kernel, cudaFuncAttributeMaxDynamicSharedMemorySize, ATTN_SMEM);

    // weight conversion (loop-invariant)
    pack_qkv_kernel<<<(NLAYER * DIM * QKVN) / 256, 256>>>(Wq, Wk, Wv, bq, bk, bv,
                                                          Wqkv_hi, Wqkv_lo, bqkv);
    conv_split_kernel<<<(NLAYER * DIM * DIM) / 256, 256>>>(Wo, Wo_hi, Wo_lo, NLAYER * DIM * DIM);
    conv_split_kernel<<<(NLAYER * DIM * FF) / 256, 256>>>(W1, W1_hi, W1_lo, NLAYER * DIM * FF);
    conv_split_kernel<<<(NLAYER * FF * DIM) / 256, 256>>>(W2, W2_hi, W2_lo, NLAYER * FF * DIM);

    const int EW = NTOK * DIM;
    embed_kernel<<<EW / 256, 256>>>(x, tok_emb, pos_emb, xemb, h);

    dim3 gQKV(QKVN / 64, NTOK / 128);   // 24 x 8  (TM=128, LN fused)
    dim3 gWo (DIM  / 64, NTOK / 64);    //  8 x 16 (TM=64)
    dim3 gF1 (FF   / 64, NTOK / 128);   // 16 x 8  (TM=128, LN fused)
    dim3 gF2 (DIM  / 64, NTOK / 64);    //  8 x 16 (TM=64)

    for (int step = 0; step < NSTEPS; step++) {
        for (int i = 0; i < NLAYER; i++) {
            const __nv_bfloat16* wqkv_h = Wqkv_hi + (size_t)i * DIM * QKVN;
            const __nv_bfloat16* wqkv_l = Wqkv_lo + (size_t)i * DIM * QKVN;
            const __nv_bfloat16* wo_h = Wo_hi + (size_t)i * DIM * DIM;
            const __nv_bfloat16* wo_l = Wo_lo + (size_t)i * DIM * DIM;
            const __nv_bfloat16* w1_h = W1_hi + (size_t)i * DIM * FF;
            const __nv_bfloat16* w1_l = W1_lo + (size_t)i * DIM * FF;
            const __nv_bfloat16* w2_h = W2_hi + (size_t)i * FF * DIM;
            const __nv_bfloat16* w2_l = W2_lo + (size_t)i * FF * DIM;

            // LN1 + QKV projection -> split bf16 (mode 4)
            gemm_tc<128, true><<<gQKV, 256>>>(nullptr, nullptr, h,
                                              ln1_g + i * DIM, ln1_b + i * DIM,
                                              wqkv_h, wqkv_l, bqkv + i * QKVN,
                                              nullptr, nullptr, qkv_hi, qkv_lo, nullptr,
                                              DIM, QKVN, 4);

            attn_kernel<<<BATCH * NHEAD * 2, 256, ATTN_SMEM>>>(qkv_hi, qkv_lo, o_hi, o_lo);

            // h = h + o @ Wo + bo (mode 2)
            gemm_tc<64, false><<<gWo, 256>>>(o_hi, o_lo, nullptr, nullptr, nullptr,
                                             wo_h, wo_l, bo + i * DIM,
                                             h, h, nullptr, nullptr, nullptr, DIM, DIM, 2);

            // LN2 + FFN1 relu -> split (mode 1)
            gemm_tc<128, true><<<gF1, 256>>>(nullptr, nullptr, h,
                                             ln2_g + i * DIM, ln2_b + i * DIM,
                                             w1_h, w1_l, b1 + i * FF,
                                             nullptr, nullptr, f1_hi, f1_lo, nullptr,
                                             DIM, FF, 1);
            // FFN2 + eqprop update fused (mode 3)
            gemm_tc<64, false><<<gF2, 256>>>(f1_hi, f1_lo, nullptr, nullptr, nullptr,
                                             w2_h, w2_l, b2 + i * DIM,
                                             h, h, nullptr, nullptr, xemb, FF, DIM, 3);
        }
    }

    pool_head_kernel<<<BATCH, 512>>>(h, head_w, head_b, out);
}

// round 13
// speedup vs baseline: 1.3030x; 1.3030x over previous
#include <cuda_runtime.h>
#include <cuda_bf16.h>
#include <stdint.h>
#include <math.h>

// Problem constants
#define BATCH 8
#define SEQ   128
#define NTOK  (BATCH * SEQ)      // 1024
#define DIM   512
#define NHEAD 8
#define HD    64
#define FF    1024
#define OUTD  1000
#define NLAYER 2
#define NSTEPS 20
#define ALPHA_ 0.5f
#define QKVN  (3 * DIM)          // 1536

// ---------------- scratch (device globals; no allocation) ----------------
__device__ float g_xemb[NTOK * DIM];
__device__ float g_h[NTOK * DIM];

__device__ __nv_bfloat16 g_qkv_hi[NTOK * QKVN];
__device__ __nv_bfloat16 g_qkv_lo[NTOK * QKVN];
__device__ __nv_bfloat16 g_hn_hi[NTOK * DIM];
__device__ __nv_bfloat16 g_hn_lo[NTOK * DIM];
__device__ __nv_bfloat16 g_o_hi[NTOK * DIM];
__device__ __nv_bfloat16 g_o_lo[NTOK * DIM];
__device__ __nv_bfloat16 g_f1_hi[NTOK * FF];
__device__ __nv_bfloat16 g_f1_lo[NTOK * FF];

// split weights (converted once per launch call)
__device__ __nv_bfloat16 g_Wqkv_hi[NLAYER * DIM * QKVN];
__device__ __nv_bfloat16 g_Wqkv_lo[NLAYER * DIM * QKVN];
__device__ float         g_bqkv  [NLAYER * QKVN];
__device__ __nv_bfloat16 g_Wo_hi[NLAYER * DIM * DIM];
__device__ __nv_bfloat16 g_Wo_lo[NLAYER * DIM * DIM];
__device__ __nv_bfloat16 g_W1_hi[NLAYER * DIM * FF];
__device__ __nv_bfloat16 g_W1_lo[NLAYER * DIM * FF];
__device__ __nv_bfloat16 g_W2_hi[NLAYER * FF * DIM];
__device__ __nv_bfloat16 g_W2_lo[NLAYER * FF * DIM];

__device__ __forceinline__ void split2(float x, __nv_bfloat16& hi, __nv_bfloat16& lo) {
    hi = __float2bfloat16(x);
    lo = __float2bfloat16(x - __bfloat162float(hi));
}
__device__ __forceinline__ unsigned pack_bf2(__nv_bfloat16 a, __nv_bfloat16 b) {
    __nv_bfloat162 t; t.x = a; t.y = b;
    return *(unsigned*)&t;
}

// ---------------- single merged weight-prep kernel ----------------
// covers: Wqkv pack+split (+bias pack), Wo, W1, W2 splits
#define WQKV_ELEMS (NLAYER * DIM * QKVN)   // 1,572,864
#define WO_ELEMS   (NLAYER * DIM * DIM)    //   524,288
#define W1_ELEMS   (NLAYER * DIM * FF)     // 1,048,576
#define W2_ELEMS   (NLAYER * FF * DIM)     // 1,048,576
#define PREP_TOTAL (WQKV_ELEMS + WO_ELEMS + W1_ELEMS + W2_ELEMS)  // 4,194,304

__global__ void prep_weights_kernel(
    const float* __restrict__ Wq, const float* __restrict__ Wk, const float* __restrict__ Wv,
    const float* __restrict__ bq, const float* __restrict__ bk, const float* __restrict__ bv,
    const float* __restrict__ Wo, const float* __restrict__ W1, const float* __restrict__ W2,
    __nv_bfloat16* __restrict__ Wqkv_h, __nv_bfloat16* __restrict__ Wqkv_l,
    float* __restrict__ bqkv,
    __nv_bfloat16* __restrict__ Wo_h, __nv_bfloat16* __restrict__ Wo_l,
    __nv_bfloat16* __restrict__ W1_h, __nv_bfloat16* __restrict__ W1_l,
    __nv_bfloat16* __restrict__ W2_h, __nv_bfloat16* __restrict__ W2_l) {
    int i = blockIdx.x * 256 + threadIdx.x;
    if (i < WQKV_ELEMS) {
        int layer = i / (DIM * QKVN);
        int rem = i % (DIM * QKVN);
        int r = rem / QKVN, c = rem % QKVN;
        const float* src = (c < DIM) ? Wq : (c < 2 * DIM) ? Wk : Wv;
        float v = src[layer * DIM * DIM + r * DIM + (c & (DIM - 1))];
        split2(v, Wqkv_h[i], Wqkv_l[i]);
        if (i < NLAYER * QKVN) {
            int l2 = i / QKVN, c2 = i % QKVN;
            const float* bsrc = (c2 < DIM) ? bq : (c2 < 2 * DIM) ? bk : bv;
            bqkv[i] = bsrc[l2 * DIM + (c2 & (DIM - 1))];
        }
        return;
    }
    int j = i - WQKV_ELEMS;
    if (j < WO_ELEMS) { split2(Wo[j], Wo_h[j], Wo_l[j]); return; }
    j -= WO_ELEMS;
    if (j < W1_ELEMS) { split2(W1[j], W1_h[j], W1_l[j]); return; }
    j -= W1_ELEMS;
    if (j < W2_ELEMS) { split2(W2[j], W2_h[j], W2_l[j]); }
}

// ---------------- embed + zero h ----------------
__global__ void embed_kernel(const int* __restrict__ x, const float* __restrict__ tok,
                             const float* __restrict__ pos, float* __restrict__ xemb,
                             float* __restrict__ h) {
    int i = blockIdx.x * blockDim.x + threadIdx.x;
    int token = i >> 9;
    int d = i & 511;
    int s = token & (SEQ - 1);
    xemb[i] = tok[(long)x[token] * DIM + d] + pos[s * DIM + d];
    h[i] = 0.0f;
}

// ---------------- layernorm, warp-per-row (scalar loads + shfl; R11-proven math) ----------------
__global__ __launch_bounds__(256)
void ln_kernel(const float* __restrict__ h, const float* __restrict__ g,
               const float* __restrict__ b,
               __nv_bfloat16* __restrict__ out_hi,
               __nv_bfloat16* __restrict__ out_lo) {
    int warp = threadIdx.x >> 5, lane = threadIdx.x & 31;
    int t = blockIdx.x * 8 + warp;           // grid = NTOK/8 = 128 blocks
    const float* row = h + (size_t)t * DIM;

    float v[16];
    float s = 0.0f;
    #pragma unroll
    for (int j = 0; j < 16; j++) { v[j] = row[lane + 32 * j]; s += v[j]; }
    #pragma unroll
    for (int o = 16; o; o >>= 1) s += __shfl_xor_sync(0xffffffffu, s, o);
    float mu = s * (1.0f / DIM);
    float vs = 0.0f;
    #pragma unroll
    for (int j = 0; j < 16; j++) { float dv = v[j] - mu; vs += dv * dv; }
    #pragma unroll
    for (int o = 16; o; o >>= 1) vs += __shfl_xor_sync(0xffffffffu, vs, o);
    float r = rsqrtf(vs * (1.0f / DIM) + 1e-5f);

    #pragma unroll
    for (int j = 0; j < 16; j++) {
        int c = lane + 32 * j;
        float o0 = (v[j] - mu) * r * g[c] + b[c];
        split2(o0, out_hi[(size_t)t * DIM + c], out_lo[(size_t)t * DIM + c]);
    }
}

// ---------------- MMA primitives (validated R3/R4/R9) ----------------
#define LDSM4(R0,R1,R2,R3,ADDR) \
    asm volatile("ldmatrix.sync.aligned.m8n8.x4.shared.b16 {%0,%1,%2,%3},[%4];" \
                 : "=r"(R0),"=r"(R1),"=r"(R2),"=r"(R3) : "r"(ADDR))
#define LDSM4T(R0,R1,R2,R3,ADDR) \
    asm volatile("ldmatrix.sync.aligned.m8n8.x4.trans.shared.b16 {%0,%1,%2,%3},[%4];" \
                 : "=r"(R0),"=r"(R1),"=r"(R2),"=r"(R3) : "r"(ADDR))
#define MMA16816(D,A,B0,B1) \
    asm volatile("mma.sync.aligned.m16n8k16.row.col.f32.bf16.bf16.f32 " \
                 "{%0,%1,%2,%3},{%4,%5,%6,%7},{%8,%9},{%0,%1,%2,%3};" \
                 : "+f"((D)[0]),"+f"((D)[1]),"+f"((D)[2]),"+f"((D)[3]) \
                 : "r"((A)[0]),"r"((A)[1]),"r"((A)[2]),"r"((A)[3]),"r"(B0),"r"(B1))

// ---------------- tensor-core GEMM (R9 verbatim — FROZEN) ----------------
// modes: 1: relu+split  2: Cf=v+res  3: eqprop update  4: split (no relu)
template<int TM>
__global__ __launch_bounds__(256)
void gemm_tc(const __nv_bfloat16* __restrict__ Ah, const __nv_bfloat16* __restrict__ Al,
             const __nv_bfloat16* __restrict__ Bh, const __nv_bfloat16* __restrict__ Bl,
             const float* __restrict__ bias, const float* __restrict__ res,
             float* __restrict__ Cf, __nv_bfloat16* __restrict__ Ch,
             __nv_bfloat16* __restrict__ Cl, const float* __restrict__ xemb,
             int K, int N, int mode) {
    constexpr int NW  = (TM == 128) ? 4 : 2;   // n8 tiles per warp
    constexpr int WMW = TM / 32;               // warps along M
    __shared__ __nv_bfloat16 sAh[TM][40], sAl[TM][40];
    __shared__ __nv_bfloat16 sBh[32][72],  sBl[32][72];

    int tid = threadIdx.x;
    int m0 = blockIdx.y * TM, n0 = blockIdx.x * 64;
    int warp = tid >> 5, lane = tid & 31;
    int wm = (warp % WMW) * 32;
    int wn = (warp / WMW) * (NW * 8);

    float d[2][NW][4];
    #pragma unroll
    for (int a = 0; a < 2; a++)
        #pragma unroll
        for (int bb = 0; bb < NW; bb++)
            #pragma unroll
            for (int c = 0; c < 4; c++) d[a][bb][c] = 0.0f;

    for (int k0 = 0; k0 < K; k0 += 32) {
        #pragma unroll
        for (int i = 0; i < TM / 64; i++) {
            int idx = tid + i * 256;
            int r = idx >> 2, kc = (idx & 3) * 8;
            size_t go = (size_t)(m0 + r) * K + k0 + kc;
            *(uint4*)&sAh[r][kc] = *(const uint4*)(Ah + go);
            *(uint4*)&sAl[r][kc] = *(const uint4*)(Al + go);
        }
        {
            int r = tid >> 3, nc = (tid & 7) * 8;
            size_t go = (size_t)(k0 + r) * N + n0 + nc;
            *(uint4*)&sBh[r][nc] = *(const uint4*)(Bh + go);
            *(uint4*)&sBl[r][nc] = *(const uint4*)(Bl + go);
        }
        __syncthreads();

        #pragma unroll
        for (int kk = 0; kk < 32; kk += 16) {
            unsigned ah[2][4], al[2][4], bh[2][4], bl[2][4];
            #pragma unroll
            for (int mi = 0; mi < 2; mi++) {
                unsigned adh = (unsigned)__cvta_generic_to_shared(
                    &sAh[wm + mi * 16 + (lane & 15)][kk + (lane >> 4) * 8]);
                LDSM4(ah[mi][0], ah[mi][1], ah[mi][2], ah[mi][3], adh);
                unsigned adl = (unsigned)__cvta_generic_to_shared(
                    &sAl[wm + mi * 16 + (lane & 15)][kk + (lane >> 4) * 8]);
                LDSM4(al[mi][0], al[mi][1], al[mi][2], al[mi][3], adl);
            }
            #pragma unroll
            for (int nj = 0; nj < NW / 2; nj++) {
                unsigned bdh = (unsigned)__cvta_generic_to_shared(
                    &sBh[kk + (lane & 15)][wn + nj * 16 + (lane >> 4) * 8]);
                LDSM4T(bh[nj][0], bh[nj][1], bh[nj][2], bh[nj][3], bdh);
                unsigned bdl = (unsigned)__cvta_generic_to_shared(
                    &sBl[kk + (lane & 15)][wn + nj * 16 + (lane >> 4) * 8]);
                LDSM4T(bl[nj][0], bl[nj][1], bl[nj][2], bl[nj][3], bdl);
            }
            #pragma unroll
            for (int mi = 0; mi < 2; mi++)
                #pragma unroll
                for (int n8 = 0; n8 < NW; n8++) {
                    unsigned b0h = bh[n8 >> 1][(n8 & 1) * 2 + 0];
                    unsigned b1h = bh[n8 >> 1][(n8 & 1) * 2 + 1];
                    unsigned b0l = bl[n8 >> 1][(n8 & 1) * 2 + 0];
                    unsigned b1l = bl[n8 >> 1][(n8 & 1) * 2 + 1];
                    MMA16816(d[mi][n8], ah[mi], b0h, b1h);
                    MMA16816(d[mi][n8], ah[mi], b0l, b1l);
                    MMA16816(d[mi][n8], al[mi], b0h, b1h);
                }
        }
        __syncthreads();
    }

    // epilogue
    #pragma unroll
    for (int mi = 0; mi < 2; mi++)
        #pragma unroll
        for (int n8 = 0; n8 < NW; n8++) {
            int r0 = m0 + wm + mi * 16 + (lane >> 2);
            int c0 = n0 + wn + n8 * 8 + (lane & 3) * 2;
            float b0v = bias[c0], b1v = bias[c0 + 1];
            #pragma unroll
            for (int half = 0; half < 2; half++) {
                int rr = r0 + half * 8;
                float v0 = d[mi][n8][half * 2 + 0] + b0v;
                float v1 = d[mi][n8][half * 2 + 1] + b1v;
                size_t idx = (size_t)rr * N + c0;
                if (mode == 1) {
                    v0 = fmaxf(v0, 0.0f); v1 = fmaxf(v1, 0.0f);
                    split2(v0, Ch[idx], Cl[idx]);
                    split2(v1, Ch[idx + 1], Cl[idx + 1]);
                } else if (mode == 2) {
                    Cf[idx] = v0 + res[idx]; Cf[idx + 1] = v1 + res[idx + 1];
                } else if (mode == 3) {
                    float h0 = res[idx], h1 = res[idx + 1];
                    float t0 = h0 + v0 + xemb[idx];
                    float t1 = h1 + v1 + xemb[idx + 1];
                    Cf[idx]     = h0 + ALPHA_ * (tanhf(t0) - h0);
                    Cf[idx + 1] = h1 + ALPHA_ * (tanhf(t1) - h1);
                } else { // 4: split, no relu
                    split2(v0, Ch[idx], Cl[idx]);
                    split2(v1, Ch[idx + 1], Cl[idx + 1]);
                }
            }
        }
}

// ---------------- fused tensor-core attention (R4/R9 verbatim) ----------------
__global__ __launch_bounds__(256)
void attn_kernel(const __nv_bfloat16* __restrict__ qkv_hi,
                 const __nv_bfloat16* __restrict__ qkv_lo,
                 __nv_bfloat16* __restrict__ o_hi, __nv_bfloat16* __restrict__ o_lo) {
    extern __shared__ char sm_raw[];
    __nv_bfloat16* sQh = (__nv_bfloat16*)sm_raw;            // [64][72]
    __nv_bfloat16* sQl = sQh + 64 * 72;
    __nv_bfloat16* sKh = sQl + 64 * 72;                     // K^T [64 d][136 s]
    __nv_bfloat16* sKl = sKh + 64 * 136;
    __nv_bfloat16* sVh = sKl + 64 * 136;                    // [128 s][72 d]
    __nv_bfloat16* sVl = sVh + 128 * 72;
    float* sO   = (float*)(sVl + 128 * 72);                 // [4 mt][16][64]
    float* sMax = sO + 4 * 16 * 64;
    float* sSum = sMax + 128;

    int blk = blockIdx.x;
    int bh = blk >> 1, qhalf = blk & 1;
    int b = bh >> 3, hh = bh & 7;
    int tid = threadIdx.x, warp = tid >> 5, lane = tid & 31;
    int q0 = qhalf * 64;

    for (int i = tid; i < 64 * 64; i += 256) {
        int r = i >> 6, dd = i & 63;
        size_t g = (size_t)(b * SEQ + q0 + r) * QKVN + hh * HD + dd;
        sQh[r * 72 + dd] = qkv_hi[g];
        sQl[r * 72 + dd] = qkv_lo[g];
    }
    for (int i = tid; i < 128 * 64; i += 256) {
        int s = i >> 6, dd = i & 63;
        size_t g = (size_t)(b * SEQ + s) * QKVN + DIM + hh * HD + dd;
        sKh[dd * 136 + s] = qkv_hi[g];
        sKl[dd * 136 + s] = qkv_lo[g];
    }
    for (int i = tid; i < 128 * 64; i += 256) {
        int s = i >> 6, dd = i & 63;
        size_t g = (size_t)(b * SEQ + s) * QKVN + 2 * DIM + hh * HD + dd;
        sVh[s * 72 + dd] = qkv_hi[g];
        sVl[s * 72 + dd] = qkv_lo[g];
    }
    __syncthreads();

    int mt = warp >> 1;
    int kh = warp & 1;

    float s[8][4];
    #pragma unroll
    for (int a = 0; a < 8; a++)
        #pragma unroll
        for (int c = 0; c < 4; c++) s[a][c] = 0.0f;

    #pragma unroll
    for (int d0 = 0; d0 < 64; d0 += 16) {
        unsigned qh4[4], ql4[4];
        unsigned aaddr = (unsigned)__cvta_generic_to_shared(
            &sQh[(mt * 16 + (lane & 15)) * 72 + d0 + (lane >> 4) * 8]);
        LDSM4(qh4[0], qh4[1], qh4[2], qh4[3], aaddr);
        unsigned aaddr2 = (unsigned)__cvta_generic_to_shared(
            &sQl[(mt * 16 + (lane & 15)) * 72 + d0 + (lane >> 4) * 8]);
        LDSM4(ql4[0], ql4[1], ql4[2], ql4[3], aaddr2);
        #pragma unroll
        for (int nj = 0; nj < 4; nj++) {
            unsigned kbh[4], kbl[4];
            unsigned baddr = (unsigned)__cvta_generic_to_shared(
                &sKh[(d0 + (lane & 15)) * 136 + kh * 64 + nj * 16 + (lane >> 4) * 8]);
            LDSM4T(kbh[0], kbh[1], kbh[2], kbh[3], baddr);
            unsigned baddr2 = (unsigned)__cvta_generic_to_shared(
                &sKl[(d0 + (lane & 15)) * 136 + kh * 64 + nj * 16 + (lane >> 4) * 8]);
            LDSM4T(kbl[0], kbl[1], kbl[2], kbl[3], baddr2);
            MMA16816(s[2 * nj],     qh4, kbh[0], kbh[1]);
            MMA16816(s[2 * nj],     qh4, kbl[0], kbl[1]);
            MMA16816(s[2 * nj],     ql4, kbh[0], kbh[1]);
            MMA16816(s[2 * nj + 1], qh4, kbh[2], kbh[3]);
            MMA16816(s[2 * nj + 1], qh4, kbl[2], kbl[3]);
            MMA16816(s[2 * nj + 1], ql4, kbh[2], kbh[3]);
        }
    }

    const float scale = 0.125f;
    float mlo = -1e30f, mhi = -1e30f;
    #pragma unroll
    for (int n8 = 0; n8 < 8; n8++) {
        #pragma unroll
        for (int c = 0; c < 4; c++) s[n8][c] *= scale;
        mlo = fmaxf(mlo, fmaxf(s[n8][0], s[n8][1]));
        mhi = fmaxf(mhi, fmaxf(s[n8][2], s[n8][3]));
    }
    #pragma unroll
    for (int o = 1; o <= 2; o <<= 1) {
        mlo = fmaxf(mlo, __shfl_xor_sync(0xffffffffu, mlo, o));
        mhi = fmaxf(mhi, __shfl_xor_sync(0xffffffffu, mhi, o));
    }
    int rl = lane >> 2;
    if ((lane & 3) == 0) {
        sMax[(mt * 2 + kh) * 16 + rl]     = mlo;
        sMax[(mt * 2 + kh) * 16 + rl + 8] = mhi;
    }
    __syncthreads();
    float Ml = fmaxf(sMax[mt * 32 + rl],     sMax[mt * 32 + 16 + rl]);
    float Mh = fmaxf(sMax[mt * 32 + 8 + rl], sMax[mt * 32 + 24 + rl]);

    float slo = 0.0f, shi = 0.0f;
    #pragma unroll
    for (int n8 = 0; n8 < 8; n8++) {
        s[n8][0] = __expf(s[n8][0] - Ml); slo += s[n8][0];
        s[n8][1] = __expf(s[n8][1] - Ml); slo += s[n8][1];
        s[n8][2] = __expf(s[n8][2] - Mh); shi += s[n8][2];
        s[n8][3] = __expf(s[n8][3] - Mh); shi += s[n8][3];
    }
    #pragma unroll
    for (int o = 1; o <= 2; o <<= 1) {
        slo += __shfl_xor_sync(0xffffffffu, slo, o);
        shi += __shfl_xor_sync(0xffffffffu, shi, o);
    }
    if ((lane & 3) == 0) {
        sSum[(mt * 2 + kh) * 16 + rl]     = slo;
        sSum[(mt * 2 + kh) * 16 + rl + 8] = shi;
    }
    __syncthreads();
    float invl = 1.0f / (sSum[mt * 32 + rl]     + sSum[mt * 32 + 16 + rl]);
    float invh = 1.0f / (sSum[mt * 32 + 8 + rl] + sSum[mt * 32 + 24 + rl]);

    float o_acc[8][4];
    #pragma unroll
    for (int a = 0; a < 8; a++)
        #pragma unroll
        for (int c = 0; c < 4; c++) o_acc[a][c] = 0.0f;

    #pragma unroll
    for (int kk = 0; kk < 4; kk++) {
        float p[8];
        p[0] = s[2 * kk][0] * invl;     p[1] = s[2 * kk][1] * invl;
        p[2] = s[2 * kk][2] * invh;     p[3] = s[2 * kk][3] * invh;
        p[4] = s[2 * kk + 1][0] * invl; p[5] = s[2 * kk + 1][1] * invl;
        p[6] = s[2 * kk + 1][2] * invh; p[7] = s[2 * kk + 1][3] * invh;
        __nv_bfloat16 phh[8], pll[8];
        #pragma unroll
        for (int j = 0; j < 8; j++) split2(p[j], phh[j], pll[j]);
        unsigned pah[4], pal[4];
        #pragma unroll
        for (int j = 0; j < 4; j++) {
            pah[j] = pack_bf2(phh[2 * j], phh[2 * j + 1]);
            pal[j] = pack_bf2(pll[2 * j], pll[2 * j + 1]);
        }
        #pragma unroll
        for (int nj = 0; nj < 4; nj++) {
            unsigned vbh[4], vbl[4];
            unsigned baddr = (unsigned)__cvta_generic_to_shared(
                &sVh[(kh * 64 + kk * 16 + (lane & 15)) * 72 + nj * 16 + (lane >> 4) * 8]);
            LDSM4T(vbh[0], vbh[1], vbh[2], vbh[3], baddr);
            unsigned baddr2 = (unsigned)__cvta_generic_to_shared(
                &sVl[(kh * 64 + kk * 16 + (lane & 15)) * 72 + nj * 16 + (lane >> 4) * 8]);
            LDSM4T(vbl[0], vbl[1], vbl[2], vbl[3], baddr2);
            MMA16816(o_acc[2 * nj],     pah, vbh[0], vbh[1]);
            MMA16816(o_acc[2 * nj],     pah, vbl[0], vbl[1]);
            MMA16816(o_acc[2 * nj],     pal, vbh[0], vbh[1]);
            MMA16816(o_acc[2 * nj + 1], pah, vbh[2], vbh[3]);
            MMA16816(o_acc[2 * nj + 1], pah, vbl[2], vbl[3]);
            MMA16816(o_acc[2 * nj + 1], pal, vbh[2], vbh[3]);
        }
    }

    if (kh == 1) {
        #pragma unroll
        for (int n8 = 0; n8 < 8; n8++) {
            int c = n8 * 8 + (lane & 3) * 2;
            sO[mt * 1024 + rl * 64 + c]           = o_acc[n8][0];
            sO[mt * 1024 + rl * 64 + c + 1]       = o_acc[n8][1];
            sO[mt * 1024 + (rl + 8) * 64 + c]     = o_acc[n8][2];
            sO[mt * 1024 + (rl + 8) * 64 + c + 1] = o_acc[n8][3];
        }
    }
    __syncthreads();
    if (kh == 0) {
        #pragma unroll
        for (int n8 = 0; n8 < 8; n8++) {
            int c = n8 * 8 + (lane & 3) * 2;
            float v0 = o_acc[n8][0] + sO[mt * 1024 + rl * 64 + c];
            float v1 = o_acc[n8][1] + sO[mt * 1024 + rl * 64 + c + 1];
            float v2 = o_acc[n8][2] + sO[mt * 1024 + (rl + 8) * 64 + c];
            float v3 = o_acc[n8][3] + sO[mt * 1024 + (rl + 8) * 64 + c + 1];
            size_t g0 = (size_t)(b * SEQ + q0 + mt * 16 + rl) * DIM + hh * HD + c;
            size_t g1 = (size_t)(b * SEQ + q0 + mt * 16 + rl + 8) * DIM + hh * HD + c;
            split2(v0, o_hi[g0], o_lo[g0]);
            split2(v1, o_hi[g0 + 1], o_lo[g0 + 1]);
            split2(v2, o_hi[g1], o_lo[g1]);
            split2(v3, o_hi[g1 + 1], o_lo[g1 + 1]);
        }
    }
}

// ---------------- fused mean-pool + head (R9, passing) ----------------
__global__ void pool_head_kernel(const float* __restrict__ h, const float* __restrict__ W,
                                 const float* __restrict__ bias, float* __restrict__ out) {
    __shared__ float sp[DIM];
    int b = blockIdx.x;                  // 8 blocks
    int tid = threadIdx.x;               // 512
    float s = 0.0f;
    for (int si = 0; si < SEQ; si++) s += h[(b * SEQ + si) * DIM + tid];
    sp[tid] = s * (1.0f / SEQ);
    __syncthreads();
    for (int o = tid; o < OUTD; o += 512) {
        float acc = bias[o];
        #pragma unroll 4
        for (int d = 0; d < DIM; d++) acc += sp[d] * W[d * OUTD + o];
        out[b * OUTD + o] = acc;
    }
}

// ---------------- launch ----------------
extern "C" void kernel_launch(void* const* d_in, const int* in_sizes, int n_in,
                              void* d_out, int out_size) {
    const int*   x       = (const int*)  d_in[0];
    // d_in[1] = steps (fixed 20; unrolled on host)
    const float* tok_emb = (const float*)d_in[2];
    const float* pos_emb = (const float*)d_in[3];
    const float* Wq = (const float*)d_in[4];
    const float* bq = (const float*)d_in[5];
    const float* Wk = (const float*)d_in[6];
    const float* bk = (const float*)d_in[7];
    const float* Wv = (const float*)d_in[8];
    const float* bv = (const float*)d_in[9];
    const float* Wo = (const float*)d_in[10];
    const float* bo = (const float*)d_in[11];
    const float* W1 = (const float*)d_in[12];
    const float* b1 = (const float*)d_in[13];
    const float* W2 = (const float*)d_in[14];
    const float* b2 = (const float*)d_in[15];
    const float* ln1_g = (const float*)d_in[16];
    const float* ln1_b = (const float*)d_in[17];
    const float* ln2_g = (const float*)d_in[18];
    const float* ln2_b = (const float*)d_in[19];
    const float* head_w = (const float*)d_in[20];
    const float* head_b = (const float*)d_in[21];
    float* out = (float*)d_out;

    float *xemb, *h, *bqkv;
    __nv_bfloat16 *qkv_hi, *qkv_lo, *hn_hi, *hn_lo, *o_hi, *o_lo, *f1_hi, *f1_lo;
    __nv_bfloat16 *Wqkv_hi, *Wqkv_lo, *Wo_hi, *Wo_lo, *W1_hi, *W1_lo, *W2_hi, *W2_lo;
    cudaGetSymbolAddress((void**)&xemb,   g_xemb);
    cudaGetSymbolAddress((void**)&h,      g_h);
    cudaGetSymbolAddress((void**)&bqkv,   g_bqkv);
    cudaGetSymbolAddress((void**)&qkv_hi, g_qkv_hi);
    cudaGetSymbolAddress((void**)&qkv_lo, g_qkv_lo);
    cudaGetSymbolAddress((void**)&hn_hi,  g_hn_hi);
    cudaGetSymbolAddress((void**)&hn_lo,  g_hn_lo);
    cudaGetSymbolAddress((void**)&o_hi,   g_o_hi);
    cudaGetSymbolAddress((void**)&o_lo,   g_o_lo);
    cudaGetSymbolAddress((void**)&f1_hi,  g_f1_hi);
    cudaGetSymbolAddress((void**)&f1_lo,  g_f1_lo);
    cudaGetSymbolAddress((void**)&Wqkv_hi, g_Wqkv_hi);
    cudaGetSymbolAddress((void**)&Wqkv_lo, g_Wqkv_lo);
    cudaGetSymbolAddress((void**)&Wo_hi,  g_Wo_hi);
    cudaGetSymbolAddress((void**)&Wo_lo,  g_Wo_lo);
    cudaGetSymbolAddress((void**)&W1_hi,  g_W1_hi);
    cudaGetSymbolAddress((void**)&W1_lo,  g_W1_lo);
    cudaGetSymbolAddress((void**)&W2_hi,  g_W2_hi);
    cudaGetSymbolAddress((void**)&W2_lo,  g_W2_lo);

    const int ATTN_SMEM = (2 * (64 * 72) + 2 * (64 * 136) + 2 * (128 * 72)) * 2
                        + (4 * 16 * 64 + 256) * 4;   // 107,520 B
    cudaFuncSetAttribute(attn_kernel, cudaFuncAttributeMaxDynamicSharedMemorySize, ATTN_SMEM);

    // merged weight conversion (1 launch)
    prep_weights_kernel<<<PREP_TOTAL / 256, 256>>>(Wq, Wk, Wv, bq, bk, bv, Wo, W1, W2,
                                                   Wqkv_hi, Wqkv_lo, bqkv,
                                                   Wo_hi, Wo_lo, W1_hi, W1_lo, W2_hi, W2_lo);

    const int EW = NTOK * DIM;
    embed_kernel<<<EW / 256, 256>>>(x, tok_emb, pos_emb, xemb, h);

    dim3 gQKV(QKVN / 64, NTOK / 128);   // 24 x 8  (TM=128)
    dim3 gWo (DIM  / 64, NTOK / 64);    //  8 x 16 (TM=64)
    dim3 gF1 (FF   / 64, NTOK / 128);   // 16 x 8  (TM=128)
    dim3 gF2 (DIM  / 64, NTOK / 64);    //  8 x 16 (TM=64)

    for (int step = 0; step < NSTEPS; step++) {
        for (int i = 0; i < NLAYER; i++) {
            const __nv_bfloat16* wqkv_h = Wqkv_hi + (size_t)i * DIM * QKVN;
            const __nv_bfloat16* wqkv_l = Wqkv_lo + (size_t)i * DIM * QKVN;
            const __nv_bfloat16* wo_h = Wo_hi + (size_t)i * DIM * DIM;
            const __nv_bfloat16* wo_l = Wo_lo + (size_t)i * DIM * DIM;
            const __nv_bfloat16* w1_h = W1_hi + (size_t)i * DIM * FF;
            const __nv_bfloat16* w1_l = W1_lo + (size_t)i * DIM * FF;
            const __nv_bfloat16* w2_h = W2_hi + (size_t)i * FF * DIM;
            const __nv_bfloat16* w2_l = W2_lo + (size_t)i * FF * DIM;

            ln_kernel<<<NTOK / 8, 256>>>(h, ln1_g + i * DIM, ln1_b + i * DIM, hn_hi, hn_lo);

            // QKV projection -> split bf16 (mode 4)
            gemm_tc<128><<<gQKV, 256>>>(hn_hi, hn_lo, wqkv_h, wqkv_l, bqkv + i * QKVN,
                                        nullptr, nullptr, qkv_hi, qkv_lo, nullptr,
                                        DIM, QKVN, 4);

            attn_kernel<<<BATCH * NHEAD * 2, 256, ATTN_SMEM>>>(qkv_hi, qkv_lo, o_hi, o_lo);

            // h = h + o @ Wo + bo (mode 2)
            gemm_tc<64><<<gWo, 256>>>(o_hi, o_lo, wo_h, wo_l, bo + i * DIM,
                                      h, h, nullptr, nullptr, nullptr, DIM, DIM, 2);

            ln_kernel<<<NTOK / 8, 256>>>(h, ln2_g + i * DIM, ln2_b + i * DIM, hn_hi, hn_lo);

            // FFN1 relu -> split (mode 1)
            gemm_tc<128><<<gF1, 256>>>(hn_hi, hn_lo, w1_h, w1_l, b1 + i * FF,
                                       nullptr, nullptr, f1_hi, f1_lo, nullptr,
                                       DIM, FF, 1);
            // FFN2 + eqprop update fused (mode 3)
            gemm_tc<64><<<gF2, 256>>>(f1_hi, f1_lo, w2_h, w2_l, b2 + i * DIM,
                                      h, h, nullptr, nullptr, xemb, FF, DIM, 3);
        }
    }

    pool_head_kernel<<<BATCH, 512>>>(h, head_w, head_b, out);
}

// round 14
// speedup vs baseline: 1.4575x; 1.1186x over previous
#include <cuda_runtime.h>
#include <cuda_bf16.h>
#include <stdint.h>
#include <math.h>

// Problem constants
#define BATCH 8
#define SEQ   128
#define NTOK  (BATCH * SEQ)      // 1024
#define DIM   512
#define NHEAD 8
#define HD    64
#define FF    1024
#define OUTD  1000
#define NLAYER 2
#define NSTEPS 20
#define ALPHA_ 0.5f
#define QKVN  (3 * DIM)          // 1536

// ---------------- scratch (device globals; no allocation) ----------------
__device__ float g_xemb[NTOK * DIM];
__device__ float g_h[NTOK * DIM];

__device__ __nv_bfloat16 g_qkv_hi[NTOK * QKVN];
__device__ __nv_bfloat16 g_qkv_lo[NTOK * QKVN];
__device__ __nv_bfloat16 g_hn_hi[NTOK * DIM];
__device__ __nv_bfloat16 g_hn_lo[NTOK * DIM];
__device__ __nv_bfloat16 g_o_hi[NTOK * DIM];
__device__ __nv_bfloat16 g_o_lo[NTOK * DIM];
__device__ __nv_bfloat16 g_f1_hi[NTOK * FF];
__device__ __nv_bfloat16 g_f1_lo[NTOK * FF];

// split weights (converted once per launch call)
__device__ __nv_bfloat16 g_Wqkv_hi[NLAYER * DIM * QKVN];
__device__ __nv_bfloat16 g_Wqkv_lo[NLAYER * DIM * QKVN];
__device__ float         g_bqkv  [NLAYER * QKVN];
__device__ __nv_bfloat16 g_Wo_hi[NLAYER * DIM * DIM];
__device__ __nv_bfloat16 g_Wo_lo[NLAYER * DIM * DIM];
__device__ __nv_bfloat16 g_W1_hi[NLAYER * DIM * FF];
__device__ __nv_bfloat16 g_W1_lo[NLAYER * DIM * FF];
__device__ __nv_bfloat16 g_W2_hi[NLAYER * FF * DIM];
__device__ __nv_bfloat16 g_W2_lo[NLAYER * FF * DIM];

__device__ __forceinline__ void split2(float x, __nv_bfloat16& hi, __nv_bfloat16& lo) {
    hi = __float2bfloat16(x);
    lo = __float2bfloat16(x - __bfloat162float(hi));
}
__device__ __forceinline__ unsigned pack_bf2(__nv_bfloat16 a, __nv_bfloat16 b) {
    __nv_bfloat162 t; t.x = a; t.y = b;
    return *(unsigned*)&t;
}

// ---------------- single merged weight-prep kernel ----------------
#define WQKV_ELEMS (NLAYER * DIM * QKVN)
#define WO_ELEMS   (NLAYER * DIM * DIM)
#define W1_ELEMS   (NLAYER * DIM * FF)
#define W2_ELEMS   (NLAYER * FF * DIM)
#define PREP_TOTAL (WQKV_ELEMS + WO_ELEMS + W1_ELEMS + W2_ELEMS)

__global__ void prep_weights_kernel(
    const float* __restrict__ Wq, const float* __restrict__ Wk, const float* __restrict__ Wv,
    const float* __restrict__ bq, const float* __restrict__ bk, const float* __restrict__ bv,
    const float* __restrict__ Wo, const float* __restrict__ W1, const float* __restrict__ W2,
    __nv_bfloat16* __restrict__ Wqkv_h, __nv_bfloat16* __restrict__ Wqkv_l,
    float* __restrict__ bqkv,
    __nv_bfloat16* __restrict__ Wo_h, __nv_bfloat16* __restrict__ Wo_l,
    __nv_bfloat16* __restrict__ W1_h, __nv_bfloat16* __restrict__ W1_l,
    __nv_bfloat16* __restrict__ W2_h, __nv_bfloat16* __restrict__ W2_l) {
    int i = blockIdx.x * 256 + threadIdx.x;
    if (i < WQKV_ELEMS) {
        int layer = i / (DIM * QKVN);
        int rem = i % (DIM * QKVN);
        int r = rem / QKVN, c = rem % QKVN;
        const float* src = (c < DIM) ? Wq : (c < 2 * DIM) ? Wk : Wv;
        float v = src[layer * DIM * DIM + r * DIM + (c & (DIM - 1))];
        split2(v, Wqkv_h[i], Wqkv_l[i]);
        if (i < NLAYER * QKVN) {
            int l2 = i / QKVN, c2 = i % QKVN;
            const float* bsrc = (c2 < DIM) ? bq : (c2 < 2 * DIM) ? bk : bv;
            bqkv[i] = bsrc[l2 * DIM + (c2 & (DIM - 1))];
        }
        return;
    }
    int j = i - WQKV_ELEMS;
    if (j < WO_ELEMS) { split2(Wo[j], Wo_h[j], Wo_l[j]); return; }
    j -= WO_ELEMS;
    if (j < W1_ELEMS) { split2(W1[j], W1_h[j], W1_l[j]); return; }
    j -= W1_ELEMS;
    if (j < W2_ELEMS) { split2(W2[j], W2_h[j], W2_l[j]); }
}

// ---------------- embed + zero h ----------------
__global__ void embed_kernel(const int* __restrict__ x, const float* __restrict__ tok,
                             const float* __restrict__ pos, float* __restrict__ xemb,
                             float* __restrict__ h) {
    int i = blockIdx.x * blockDim.x + threadIdx.x;
    int token = i >> 9;
    int d = i & 511;
    int s = token & (SEQ - 1);
    xemb[i] = tok[(long)x[token] * DIM + d] + pos[s * DIM + d];
    h[i] = 0.0f;
}

// ---------------- layernorm, warp-per-row (R13, passing) ----------------
__global__ __launch_bounds__(256)
void ln_kernel(const float* __restrict__ h, const float* __restrict__ g,
               const float* __restrict__ b,
               __nv_bfloat16* __restrict__ out_hi,
               __nv_bfloat16* __restrict__ out_lo) {
    int warp = threadIdx.x >> 5, lane = threadIdx.x & 31;
    int t = blockIdx.x * 8 + warp;
    const float* row = h + (size_t)t * DIM;

    float v[16];
    float s = 0.0f;
    #pragma unroll
    for (int j = 0; j < 16; j++) { v[j] = row[lane + 32 * j]; s += v[j]; }
    #pragma unroll
    for (int o = 16; o; o >>= 1) s += __shfl_xor_sync(0xffffffffu, s, o);
    float mu = s * (1.0f / DIM);
    float vs = 0.0f;
    #pragma unroll
    for (int j = 0; j < 16; j++) { float dv = v[j] - mu; vs += dv * dv; }
    #pragma unroll
    for (int o = 16; o; o >>= 1) vs += __shfl_xor_sync(0xffffffffu, vs, o);
    float r = rsqrtf(vs * (1.0f / DIM) + 1e-5f);

    #pragma unroll
    for (int j = 0; j < 16; j++) {
        int c = lane + 32 * j;
        float o0 = (v[j] - mu) * r * g[c] + b[c];
        split2(o0, out_hi[(size_t)t * DIM + c], out_lo[(size_t)t * DIM + c]);
    }
}

// ---------------- MMA primitives (validated R3/R4/R9) ----------------
#define LDSM4(R0,R1,R2,R3,ADDR) \
    asm volatile("ldmatrix.sync.aligned.m8n8.x4.shared.b16 {%0,%1,%2,%3},[%4];" \
                 : "=r"(R0),"=r"(R1),"=r"(R2),"=r"(R3) : "r"(ADDR))
#define LDSM4T(R0,R1,R2,R3,ADDR) \
    asm volatile("ldmatrix.sync.aligned.m8n8.x4.trans.shared.b16 {%0,%1,%2,%3},[%4];" \
                 : "=r"(R0),"=r"(R1),"=r"(R2),"=r"(R3) : "r"(ADDR))
#define MMA16816(D,A,B0,B1) \
    asm volatile("mma.sync.aligned.m16n8k16.row.col.f32.bf16.bf16.f32 " \
                 "{%0,%1,%2,%3},{%4,%5,%6,%7},{%8,%9},{%0,%1,%2,%3};" \
                 : "+f"((D)[0]),"+f"((D)[1]),"+f"((D)[2]),"+f"((D)[3]) \
                 : "r"((A)[0]),"r"((A)[1]),"r"((A)[2]),"r"((A)[3]),"r"(B0),"r"(B1))

// ---------------- tensor-core GEMM: TM=64, TK=64 (R9 load shape, fewer barriers) ----------------
// Per k-iter: each thread does 8 independent uint4 LDG->STS (same adjacent shape as R9),
// then sync, ldmatrix+MMA, sync. 8 k-iters for K=512 (was 16).
// modes: 1: relu+split  2: Cf=v+res  3: eqprop update  4: split (no relu)
__global__ __launch_bounds__(256)
void gemm_tc(const __nv_bfloat16* __restrict__ Ah, const __nv_bfloat16* __restrict__ Al,
             const __nv_bfloat16* __restrict__ Bh, const __nv_bfloat16* __restrict__ Bl,
             const float* __restrict__ bias, const float* __restrict__ res,
             float* __restrict__ Cf, __nv_bfloat16* __restrict__ Ch,
             __nv_bfloat16* __restrict__ Cl, const float* __restrict__ xemb,
             int K, int N, int mode) {
    __shared__ __align__(16) __nv_bfloat16 sAh[64][72], sAl[64][72];
    __shared__ __align__(16) __nv_bfloat16 sBh[64][72], sBl[64][72];

    int tid = threadIdx.x;
    int m0 = blockIdx.y * 64, n0 = blockIdx.x * 64;
    int warp = tid >> 5, lane = tid & 31;
    int wm = (warp & 1) * 32;            // 2 warp-rows x 32
    int wn = (warp >> 1) * 16;           // 4 warp-cols x 16

    float d[2][2][4];
    #pragma unroll
    for (int a = 0; a < 2; a++)
        #pragma unroll
        for (int bb = 0; bb < 2; bb++)
            #pragma unroll
            for (int c = 0; c < 4; c++) d[a][bb][c] = 0.0f;

    // tile load mapping: 64 rows x 64 cols = 512 uint4 slots / 256 threads = 2 each
    for (int k0 = 0; k0 < K; k0 += 64) {
        #pragma unroll
        for (int i = 0; i < 2; i++) {
            int idx = tid + i * 256;
            int r = idx >> 3, c = (idx & 7) * 8;
            size_t goA = (size_t)(m0 + r) * K + k0 + c;
            *(uint4*)&sAh[r][c] = *(const uint4*)(Ah + goA);
            *(uint4*)&sAl[r][c] = *(const uint4*)(Al + goA);
            size_t goB = (size_t)(k0 + r) * N + n0 + c;
            *(uint4*)&sBh[r][c] = *(const uint4*)(Bh + goB);
            *(uint4*)&sBl[r][c] = *(const uint4*)(Bl + goB);
        }
        __syncthreads();

        #pragma unroll
        for (int kk = 0; kk < 64; kk += 16) {
            unsigned ah[2][4], al[2][4], bh[4], bl[4];
            #pragma unroll
            for (int mi = 0; mi < 2; mi++) {
                unsigned adh = (unsigned)__cvta_generic_to_shared(
                    &sAh[wm + mi * 16 + (lane & 15)][kk + (lane >> 4) * 8]);
                LDSM4(ah[mi][0], ah[mi][1], ah[mi][2], ah[mi][3], adh);
                unsigned adl = (unsigned)__cvta_generic_to_shared(
                    &sAl[wm + mi * 16 + (lane & 15)][kk + (lane >> 4) * 8]);
                LDSM4(al[mi][0], al[mi][1], al[mi][2], al[mi][3], adl);
            }
            {
                unsigned bdh = (unsigned)__cvta_generic_to_shared(
                    &sBh[kk + (lane & 15)][wn + (lane >> 4) * 8]);
                LDSM4T(bh[0], bh[1], bh[2], bh[3], bdh);
                unsigned bdl = (unsigned)__cvta_generic_to_shared(
                    &sBl[kk + (lane & 15)][wn + (lane >> 4) * 8]);
                LDSM4T(bl[0], bl[1], bl[2], bl[3], bdl);
            }
            #pragma unroll
            for (int mi = 0; mi < 2; mi++)
                #pragma unroll
                for (int n8 = 0; n8 < 2; n8++) {
                    unsigned b0h = bh[n8 * 2 + 0];
                    unsigned b1h = bh[n8 * 2 + 1];
                    unsigned b0l = bl[n8 * 2 + 0];
                    unsigned b1l = bl[n8 * 2 + 1];
                    MMA16816(d[mi][n8], ah[mi], b0h, b1h);
                    MMA16816(d[mi][n8], ah[mi], b0l, b1l);
                    MMA16816(d[mi][n8], al[mi], b0h, b1h);
                }
        }
        __syncthreads();
    }

    // epilogue (R9 logic)
    #pragma unroll
    for (int mi = 0; mi < 2; mi++)
        #pragma unroll
        for (int n8 = 0; n8 < 2; n8++) {
            int r0 = m0 + wm + mi * 16 + (lane >> 2);
            int c0 = n0 + wn + n8 * 8 + (lane & 3) * 2;
            float b0v = bias[c0], b1v = bias[c0 + 1];
            #pragma unroll
            for (int half = 0; half < 2; half++) {
                int rr = r0 + half * 8;
                float v0 = d[mi][n8][half * 2 + 0] + b0v;
                float v1 = d[mi][n8][half * 2 + 1] + b1v;
                size_t idx = (size_t)rr * N + c0;
                if (mode == 1) {
                    v0 = fmaxf(v0, 0.0f); v1 = fmaxf(v1, 0.0f);
                    split2(v0, Ch[idx], Cl[idx]);
                    split2(v1, Ch[idx + 1], Cl[idx + 1]);
                } else if (mode == 2) {
                    Cf[idx] = v0 + res[idx]; Cf[idx + 1] = v1 + res[idx + 1];
                } else if (mode == 3) {
                    float h0 = res[idx], h1 = res[idx + 1];
                    float t0 = h0 + v0 + xemb[idx];
                    float t1 = h1 + v1 + xemb[idx + 1];
                    Cf[idx]     = h0 + ALPHA_ * (tanhf(t0) - h0);
                    Cf[idx + 1] = h1 + ALPHA_ * (tanhf(t1) - h1);
                } else { // 4: split, no relu
                    split2(v0, Ch[idx], Cl[idx]);
                    split2(v1, Ch[idx + 1], Cl[idx + 1]);
                }
            }
        }
}

// ---------------- fused tensor-core attention (R4/R9 verbatim) ----------------
__global__ __launch_bounds__(256)
void attn_kernel(const __nv_bfloat16* __restrict__ qkv_hi,
                 const __nv_bfloat16* __restrict__ qkv_lo,
                 __nv_bfloat16* __restrict__ o_hi, __nv_bfloat16* __restrict__ o_lo) {
    extern __shared__ char sm_raw[];
    __nv_bfloat16* sQh = (__nv_bfloat16*)sm_raw;            // [64][72]
    __nv_bfloat16* sQl = sQh + 64 * 72;
    __nv_bfloat16* sKh = sQl + 64 * 72;                     // K^T [64 d][136 s]
    __nv_bfloat16* sKl = sKh + 64 * 136;
    __nv_bfloat16* sVh = sKl + 64 * 136;                    // [128 s][72 d]
    __nv_bfloat16* sVl = sVh + 128 * 72;
    float* sO   = (float*)(sVl + 128 * 72);                 // [4 mt][16][64]
    float* sMax = sO + 4 * 16 * 64;
    float* sSum = sMax + 128;

    int blk = blockIdx.x;
    int bh = blk >> 1, qhalf = blk & 1;
    int b = bh >> 3, hh = bh & 7;
    int tid = threadIdx.x, warp = tid >> 5, lane = tid & 31;
    int q0 = qhalf * 64;

    for (int i = tid; i < 64 * 64; i += 256) {
        int r = i >> 6, dd = i & 63;
        size_t g = (size_t)(b * SEQ + q0 + r) * QKVN + hh * HD + dd;
        sQh[r * 72 + dd] = qkv_hi[g];
        sQl[r * 72 + dd] = qkv_lo[g];
    }
    for (int i = tid; i < 128 * 64; i += 256) {
        int s = i >> 6, dd = i & 63;
        size_t g = (size_t)(b * SEQ + s) * QKVN + DIM + hh * HD + dd;
        sKh[dd * 136 + s] = qkv_hi[g];
        sKl[dd * 136 + s] = qkv_lo[g];
    }
    for (int i = tid; i < 128 * 64; i += 256) {
        int s = i >> 6, dd = i & 63;
        size_t g = (size_t)(b * SEQ + s) * QKVN + 2 * DIM + hh * HD + dd;
        sVh[s * 72 + dd] = qkv_hi[g];
        sVl[s * 72 + dd] = qkv_lo[g];
    }
    __syncthreads();

    int mt = warp >> 1;
    int kh = warp & 1;

    float s[8][4];
    #pragma unroll
    for (int a = 0; a < 8; a++)
        #pragma unroll
        for (int c = 0; c < 4; c++) s[a][c] = 0.0f;

    #pragma unroll
    for (int d0 = 0; d0 < 64; d0 += 16) {
        unsigned qh4[4], ql4[4];
        unsigned aaddr = (unsigned)__cvta_generic_to_shared(
            &sQh[(mt * 16 + (lane & 15)) * 72 + d0 + (lane >> 4) * 8]);
        LDSM4(qh4[0], qh4[1], qh4[2], qh4[3], aaddr);
        unsigned aaddr2 = (unsigned)__cvta_generic_to_shared(
            &sQl[(mt * 16 + (lane & 15)) * 72 + d0 + (lane >> 4) * 8]);
        LDSM4(ql4[0], ql4[1], ql4[2], ql4[3], aaddr2);
        #pragma unroll
        for (int nj = 0; nj < 4; nj++) {
            unsigned kbh[4], kbl[4];
            unsigned baddr = (unsigned)__cvta_generic_to_shared(
                &sKh[(d0 + (lane & 15)) * 136 + kh * 64 + nj * 16 + (lane >> 4) * 8]);
            LDSM4T(kbh[0], kbh[1], kbh[2], kbh[3], baddr);
            unsigned baddr2 = (unsigned)__cvta_generic_to_shared(
                &sKl[(d0 + (lane & 15)) * 136 + kh * 64 + nj * 16 + (lane >> 4) * 8]);
            LDSM4T(kbl[0], kbl[1], kbl[2], kbl[3], baddr2);
            MMA16816(s[2 * nj],     qh4, kbh[0], kbh[1]);
            MMA16816(s[2 * nj],     qh4, kbl[0], kbl[1]);
            MMA16816(s[2 * nj],     ql4, kbh[0], kbh[1]);
            MMA16816(s[2 * nj + 1], qh4, kbh[2], kbh[3]);
            MMA16816(s[2 * nj + 1], qh4, kbl[2], kbl[3]);
            MMA16816(s[2 * nj + 1], ql4, kbh[2], kbh[3]);
        }
    }

    const float scale = 0.125f;
    float mlo = -1e30f, mhi = -1e30f;
    #pragma unroll
    for (int n8 = 0; n8 < 8; n8++) {
        #pragma unroll
        for (int c = 0; c < 4; c++) s[n8][c] *= scale;
        mlo = fmaxf(mlo, fmaxf(s[n8][0], s[n8][1]));
        mhi = fmaxf(mhi, fmaxf(s[n8][2], s[n8][3]));
    }
    #pragma unroll
    for (int o = 1; o <= 2; o <<= 1) {
        mlo = fmaxf(mlo, __shfl_xor_sync(0xffffffffu, mlo, o));
        mhi = fmaxf(mhi, __shfl_xor_sync(0xffffffffu, mhi, o));
    }
    int rl = lane >> 2;
    if ((lane & 3) == 0) {
        sMax[(mt * 2 + kh) * 16 + rl]     = mlo;
        sMax[(mt * 2 + kh) * 16 + rl + 8] = mhi;
    }
    __syncthreads();
    float Ml = fmaxf(sMax[mt * 32 + rl],     sMax[mt * 32 + 16 + rl]);
    float Mh = fmaxf(sMax[mt * 32 + 8 + rl], sMax[mt * 32 + 24 + rl]);

    float slo = 0.0f, shi = 0.0f;
    #pragma unroll
    for (int n8 = 0; n8 < 8; n8++) {
        s[n8][0] = __expf(s[n8][0] - Ml); slo += s[n8][0];
        s[n8][1] = __expf(s[n8][1] - Ml); slo += s[n8][1];
        s[n8][2] = __expf(s[n8][2] - Mh); shi += s[n8][2];
        s[n8][3] = __expf(s[n8][3] - Mh); shi += s[n8][3];
    }
    #pragma unroll
    for (int o = 1; o <= 2; o <<= 1) {
        slo += __shfl_xor_sync(0xffffffffu, slo, o);
        shi += __shfl_xor_sync(0xffffffffu, shi, o);
    }
    if ((lane & 3) == 0) {
        sSum[(mt * 2 + kh) * 16 + rl]     = slo;
        sSum[(mt * 2 + kh) * 16 + rl + 8] = shi;
    }
    __syncthreads();
    float invl = 1.0f / (sSum[mt * 32 + rl]     + sSum[mt * 32 + 16 + rl]);
    float invh = 1.0f / (sSum[mt * 32 + 8 + rl] + sSum[mt * 32 + 24 + rl]);

    float o_acc[8][4];
    #pragma unroll
    for (int a = 0; a < 8; a++)
        #pragma unroll
        for (int c = 0; c < 4; c++) o_acc[a][c] = 0.0f;

    #pragma unroll
    for (int kk = 0; kk < 4; kk++) {
        float p[8];
        p[0] = s[2 * kk][0] * invl;     p[1] = s[2 * kk][1] * invl;
        p[2] = s[2 * kk][2] * invh;     p[3] = s[2 * kk][3] * invh;
        p[4] = s[2 * kk + 1][0] * invl; p[5] = s[2 * kk + 1][1] * invl;
        p[6] = s[2 * kk + 1][2] * invh; p[7] = s[2 * kk + 1][3] * invh;
        __nv_bfloat16 phh[8], pll[8];
        #pragma unroll
        for (int j = 0; j < 8; j++) split2(p[j], phh[j], pll[j]);
        unsigned pah[4], pal[4];
        #pragma unroll
        for (int j = 0; j < 4; j++) {
            pah[j] = pack_bf2(phh[2 * j], phh[2 * j + 1]);
            pal[j] = pack_bf2(pll[2 * j], pll[2 * j + 1]);
        }
        #pragma unroll
        for (int nj = 0; nj < 4; nj++) {
            unsigned vbh[4], vbl[4];
            unsigned baddr = (unsigned)__cvta_generic_to_shared(
                &sVh[(kh * 64 + kk * 16 + (lane & 15)) * 72 + nj * 16 + (lane >> 4) * 8]);
            LDSM4T(vbh[0], vbh[1], vbh[2], vbh[3], baddr);
            unsigned baddr2 = (unsigned)__cvta_generic_to_shared(
                &sVl[(kh * 64 + kk * 16 + (lane & 15)) * 72 + nj * 16 + (lane >> 4) * 8]);
            LDSM4T(vbl[0], vbl[1], vbl[2], vbl[3], baddr2);
            MMA16816(o_acc[2 * nj],     pah, vbh[0], vbh[1]);
            MMA16816(o_acc[2 * nj],     pah, vbl[0], vbl[1]);
            MMA16816(o_acc[2 * nj],     pal, vbh[0], vbh[1]);
            MMA16816(o_acc[2 * nj + 1], pah, vbh[2], vbh[3]);
            MMA16816(o_acc[2 * nj + 1], pah, vbl[2], vbl[3]);
            MMA16816(o_acc[2 * nj + 1], pal, vbh[2], vbh[3]);
        }
    }

    if (kh == 1) {
        #pragma unroll
        for (int n8 = 0; n8 < 8; n8++) {
            int c = n8 * 8 + (lane & 3) * 2;
            sO[mt * 1024 + rl * 64 + c]           = o_acc[n8][0];
            sO[mt * 1024 + rl * 64 + c + 1]       = o_acc[n8][1];
            sO[mt * 1024 + (rl + 8) * 64 + c]     = o_acc[n8][2];
            sO[mt * 1024 + (rl + 8) * 64 + c + 1] = o_acc[n8][3];
        }
    }
    __syncthreads();
    if (kh == 0) {
        #pragma unroll
        for (int n8 = 0; n8 < 8; n8++) {
            int c = n8 * 8 + (lane & 3) * 2;
            float v0 = o_acc[n8][0] + sO[mt * 1024 + rl * 64 + c];
            float v1 = o_acc[n8][1] + sO[mt * 1024 + rl * 64 + c + 1];
            float v2 = o_acc[n8][2] + sO[mt * 1024 + (rl + 8) * 64 + c];
            float v3 = o_acc[n8][3] + sO[mt * 1024 + (rl + 8) * 64 + c + 1];
            size_t g0 = (size_t)(b * SEQ + q0 + mt * 16 + rl) * DIM + hh * HD + c;
            size_t g1 = (size_t)(b * SEQ + q0 + mt * 16 + rl + 8) * DIM + hh * HD + c;
            split2(v0, o_hi[g0], o_lo[g0]);
            split2(v1, o_hi[g0 + 1], o_lo[g0 + 1]);
            split2(v2, o_hi[g1], o_lo[g1]);
            split2(v3, o_hi[g1 + 1], o_lo[g1 + 1]);
        }
    }
}

// ---------------- fused mean-pool + head ----------------
__global__ void pool_head_kernel(const float* __restrict__ h, const float* __restrict__ W,
                                 const float* __restrict__ bias, float* __restrict__ out) {
    __shared__ float sp[DIM];
    int b = blockIdx.x;
    int tid = threadIdx.x;
    float s = 0.0f;
    for (int si = 0; si < SEQ; si++) s += h[(b * SEQ + si) * DIM + tid];
    sp[tid] = s * (1.0f / SEQ);
    __syncthreads();
    for (int o = tid; o < OUTD; o += 512) {
        float acc = bias[o];
        #pragma unroll 4
        for (int d = 0; d < DIM; d++) acc += sp[d] * W[d * OUTD + o];
        out[b * OUTD + o] = acc;
    }
}

// ---------------- launch ----------------
extern "C" void kernel_launch(void* const* d_in, const int* in_sizes, int n_in,
                              void* d_out, int out_size) {
    const int*   x       = (const int*)  d_in[0];
    // d_in[1] = steps (fixed 20; unrolled on host)
    const float* tok_emb = (const float*)d_in[2];
    const float* pos_emb = (const float*)d_in[3];
    const float* Wq = (const float*)d_in[4];
    const float* bq = (const float*)d_in[5];
    const float* Wk = (const float*)d_in[6];
    const float* bk = (const float*)d_in[7];
    const float* Wv = (const float*)d_in[8];
    const float* bv = (const float*)d_in[9];
    const float* Wo = (const float*)d_in[10];
    const float* bo = (const float*)d_in[11];
    const float* W1 = (const float*)d_in[12];
    const float* b1 = (const float*)d_in[13];
    const float* W2 = (const float*)d_in[14];
    const float* b2 = (const float*)d_in[15];
    const float* ln1_g = (const float*)d_in[16];
    const float* ln1_b = (const float*)d_in[17];
    const float* ln2_g = (const float*)d_in[18];
    const float* ln2_b = (const float*)d_in[19];
    const float* head_w = (const float*)d_in[20];
    const float* head_b = (const float*)d_in[21];
    float* out = (float*)d_out;

    float *xemb, *h, *bqkv;
    __nv_bfloat16 *qkv_hi, *qkv_lo, *hn_hi, *hn_lo, *o_hi, *o_lo, *f1_hi, *f1_lo;
    __nv_bfloat16 *Wqkv_hi, *Wqkv_lo, *Wo_hi, *Wo_lo, *W1_hi, *W1_lo, *W2_hi, *W2_lo;
    cudaGetSymbolAddress((void**)&xemb,   g_xemb);
    cudaGetSymbolAddress((void**)&h,      g_h);
    cudaGetSymbolAddress((void**)&bqkv,   g_bqkv);
    cudaGetSymbolAddress((void**)&qkv_hi, g_qkv_hi);
    cudaGetSymbolAddress((void**)&qkv_lo, g_qkv_lo);
    cudaGetSymbolAddress((void**)&hn_hi,  g_hn_hi);
    cudaGetSymbolAddress((void**)&hn_lo,  g_hn_lo);
    cudaGetSymbolAddress((void**)&o_hi,   g_o_hi);
    cudaGetSymbolAddress((void**)&o_lo,   g_o_lo);
    cudaGetSymbolAddress((void**)&f1_hi,  g_f1_hi);
    cudaGetSymbolAddress((void**)&f1_lo,  g_f1_lo);
    cudaGetSymbolAddress((void**)&Wqkv_hi, g_Wqkv_hi);
    cudaGetSymbolAddress((void**)&Wqkv_lo, g_Wqkv_lo);
    cudaGetSymbolAddress((void**)&Wo_hi,  g_Wo_hi);
    cudaGetSymbolAddress((void**)&Wo_lo,  g_Wo_lo);
    cudaGetSymbolAddress((void**)&W1_hi,  g_W1_hi);
    cudaGetSymbolAddress((void**)&W1_lo,  g_W1_lo);
    cudaGetSymbolAddress((void**)&W2_hi,  g_W2_hi);
    cudaGetSymbolAddress((void**)&W2_lo,  g_W2_lo);

    const int ATTN_SMEM = (2 * (64 * 72) + 2 * (64 * 136) + 2 * (128 * 72)) * 2
                        + (4 * 16 * 64 + 256) * 4;   // 107,520 B
    cudaFuncSetAttribute(attn_kernel, cudaFuncAttributeMaxDynamicSharedMemorySize, ATTN_SMEM);

    prep_weights_kernel<<<PREP_TOTAL / 256, 256>>>(Wq, Wk, Wv, bq, bk, bv, Wo, W1, W2,
                                                   Wqkv_hi, Wqkv_lo, bqkv,
                                                   Wo_hi, Wo_lo, W1_hi, W1_lo, W2_hi, W2_lo);

    const int EW = NTOK * DIM;
    embed_kernel<<<EW / 256, 256>>>(x, tok_emb, pos_emb, xemb, h);

    dim3 gQKV(QKVN / 64, NTOK / 64);    // 24 x 16 = 384 blocks
    dim3 gWo (DIM  / 64, NTOK / 64);    //  8 x 16 = 128
    dim3 gF1 (FF   / 64, NTOK / 64);    // 16 x 16 = 256
    dim3 gF2 (DIM  / 64, NTOK / 64);    //  8 x 16 = 128

    for (int step = 0; step < NSTEPS; step++) {
        for (int i = 0; i < NLAYER; i++) {
            const __nv_bfloat16* wqkv_h = Wqkv_hi + (size_t)i * DIM * QKVN;
            const __nv_bfloat16* wqkv_l = Wqkv_lo + (size_t)i * DIM * QKVN;
            const __nv_bfloat16* wo_h = Wo_hi + (size_t)i * DIM * DIM;
            const __nv_bfloat16* wo_l = Wo_lo + (size_t)i * DIM * DIM;
            const __nv_bfloat16* w1_h = W1_hi + (size_t)i * DIM * FF;
            const __nv_bfloat16* w1_l = W1_lo + (size_t)i * DIM * FF;
            const __nv_bfloat16* w2_h = W2_hi + (size_t)i * FF * DIM;
            const __nv_bfloat16* w2_l = W2_lo + (size_t)i * FF * DIM;

            ln_kernel<<<NTOK / 8, 256>>>(h, ln1_g + i * DIM, ln1_b + i * DIM, hn_hi, hn_lo);

            gemm_tc<<<gQKV, 256>>>(hn_hi, hn_lo, wqkv_h, wqkv_l, bqkv + i * QKVN,
                                   nullptr, nullptr, qkv_hi, qkv_lo, nullptr,
                                   DIM, QKVN, 4);

            attn_kernel<<<BATCH * NHEAD * 2, 256, ATTN_SMEM>>>(qkv_hi, qkv_lo, o_hi, o_lo);

            gemm_tc<<<gWo, 256>>>(o_hi, o_lo, wo_h, wo_l, bo + i * DIM,
                                  h, h, nullptr, nullptr, nullptr, DIM, DIM, 2);

            ln_kernel<<<NTOK / 8, 256>>>(h, ln2_g + i * DIM, ln2_b + i * DIM, hn_hi, hn_lo);

            gemm_tc<<<gF1, 256>>>(hn_hi, hn_lo, w1_h, w1_l, b1 + i * FF,
                                  nullptr, nullptr, f1_hi, f1_lo, nullptr,
                                  DIM, FF, 1);

            gemm_tc<<<gF2, 256>>>(f1_hi, f1_lo, w2_h, w2_l, b2 + i * DIM,
                                  h, h, nullptr, nullptr, xemb, FF, DIM, 3);
        }
    }

    pool_head_kernel<<<BATCH, 512>>>(h, head_w, head_b, out);
}